// round 1
// baseline (speedup 1.0000x reference)
#include <cuda_runtime.h>
#include <math.h>

#define P  2048
#define E  768
#define H  64
#define NQ 12

// -------- scratch (static device globals; no allocation allowed) --------
__device__ float g_q[NQ * P * H];      // [head][p][h]
__device__ float g_k[P * H];           // [p][h]
__device__ float g_v[P * H];           // [p][h]
__device__ float g_attn[P * NQ * H];   // [p][head][h]  (merged layout for out-proj)
__device__ float g_rowmax[NQ * P];
__device__ float g_rowinv[NQ * P];

// ============================================================
// K1: fused QKV projection.  GEMM: [2048 x 896], K=768.
// blockIdx.y: 0..11 -> Wq head, 12 -> Wk, 13 -> Wv. 64x64 tile, 256 thr, 4x4 micro.
// ============================================================
__global__ void qkv_kernel(const float* __restrict__ x,
                           const float* __restrict__ Wq, const float* __restrict__ bq,
                           const float* __restrict__ Wk, const float* __restrict__ bk,
                           const float* __restrict__ Wv, const float* __restrict__ bv)
{
    __shared__ __align__(16) float Xs[16][68];
    __shared__ __align__(16) float Ws[16][68];

    const int tid = threadIdx.x;
    const int m0  = blockIdx.x * 64;
    const int nt  = blockIdx.y;

    const float* W;
    const float* bias;
    if (nt < 12)      { W = Wq + (size_t)nt * 64 * E; bias = bq + nt * 64; }
    else if (nt == 12){ W = Wk; bias = bk; }
    else              { W = Wv; bias = bv; }

    const int ty = tid >> 4;         // 0..15 -> rows ty*4..+3
    const int tx = tid & 15;         // 0..15 -> cols tx*4..+3
    const int lr = tid & 63;         // loader row
    const int lk = (tid >> 6) * 4;   // loader k-quad

    float acc[4][4];
#pragma unroll
    for (int i = 0; i < 4; i++)
#pragma unroll
        for (int j = 0; j < 4; j++) acc[i][j] = 0.0f;

    for (int kk = 0; kk < E; kk += 16) {
        __syncthreads();
        {
            float4 xv = *(const float4*)&x[(size_t)(m0 + lr) * E + kk + lk];
            Xs[lk + 0][lr] = xv.x; Xs[lk + 1][lr] = xv.y;
            Xs[lk + 2][lr] = xv.z; Xs[lk + 3][lr] = xv.w;
            float4 wv = *(const float4*)&W[(size_t)lr * E + kk + lk];
            Ws[lk + 0][lr] = wv.x; Ws[lk + 1][lr] = wv.y;
            Ws[lk + 2][lr] = wv.z; Ws[lk + 3][lr] = wv.w;
        }
        __syncthreads();
#pragma unroll
        for (int k = 0; k < 16; k++) {
            float4 a = *(const float4*)&Xs[k][ty * 4];
            float4 b = *(const float4*)&Ws[k][tx * 4];
            acc[0][0] += a.x * b.x; acc[0][1] += a.x * b.y; acc[0][2] += a.x * b.z; acc[0][3] += a.x * b.w;
            acc[1][0] += a.y * b.x; acc[1][1] += a.y * b.y; acc[1][2] += a.y * b.z; acc[1][3] += a.y * b.w;
            acc[2][0] += a.z * b.x; acc[2][1] += a.z * b.y; acc[2][2] += a.z * b.z; acc[2][3] += a.z * b.w;
            acc[3][0] += a.w * b.x; acc[3][1] += a.w * b.y; acc[3][2] += a.w * b.z; acc[3][3] += a.w * b.w;
        }
    }

    const float4 bb = *(const float4*)&bias[tx * 4];
#pragma unroll
    for (int i = 0; i < 4; i++) {
        float4 o;
        o.x = acc[i][0] + bb.x; o.y = acc[i][1] + bb.y;
        o.z = acc[i][2] + bb.z; o.w = acc[i][3] + bb.w;
        const int m = m0 + ty * 4 + i;
        if (nt < 12)      *(float4*)&g_q[((size_t)nt * P + m) * H + tx * 4] = o;
        else if (nt == 12)*(float4*)&g_k[(size_t)m * H + tx * 4] = o;
        else              *(float4*)&g_v[(size_t)m * H + tx * 4] = o;
    }
}

// ============================================================
// K2: scores.  Block = (head, 16 rows). Writes raw scaled scores into the
// probs region, tracks per-row online (max, sumexp) -> g_rowmax/g_rowinv.
// 256 thr: ty = tid/64 (4 row groups of 4), tx = tid%64 (cols tx*4 in 256-tile).
// ============================================================
__global__ void scores_kernel(float* __restrict__ scores)
{
    __shared__ __align__(16) float qs[64][16];     // [h][r]
    __shared__ __align__(16) float ks[32][260];    // [h_local][c]
    __shared__ float redm[8][4];
    __shared__ float redl[8][4];

    const int tid  = threadIdx.x;
    const int head = blockIdx.y;
    const int m0   = blockIdx.x * 16;
    const int ty   = tid >> 6;   // 0..3
    const int tx   = tid & 63;   // 0..63

    // load q tile transposed
    {
        const int r  = tid & 15;
        const int hq = (tid >> 4) * 4;
        float4 qv = *(const float4*)&g_q[((size_t)head * P + m0 + r) * H + hq];
        qs[hq + 0][r] = qv.x; qs[hq + 1][r] = qv.y;
        qs[hq + 2][r] = qv.z; qs[hq + 3][r] = qv.w;
    }

    float mv[4], lv[4];
#pragma unroll
    for (int r = 0; r < 4; r++) { mv[r] = -1e30f; lv[r] = 0.0f; }

    float* srow = scores + (size_t)head * P * P;

    for (int t = 0; t < 8; t++) {
        const int n0 = t * 256;
        float acc[4][4];
#pragma unroll
        for (int i = 0; i < 4; i++)
#pragma unroll
            for (int j = 0; j < 4; j++) acc[i][j] = 0.0f;

        for (int hc = 0; hc < 64; hc += 32) {
            __syncthreads();
#pragma unroll
            for (int j8 = 0; j8 < 8; j8++) {
                float4 kv = *(const float4*)&g_k[(size_t)(n0 + tid) * H + hc + j8 * 4];
                ks[j8 * 4 + 0][tid] = kv.x; ks[j8 * 4 + 1][tid] = kv.y;
                ks[j8 * 4 + 2][tid] = kv.z; ks[j8 * 4 + 3][tid] = kv.w;
            }
            __syncthreads();
#pragma unroll
            for (int h = 0; h < 32; h++) {
                float4 a = *(const float4*)&qs[hc + h][ty * 4];
                float4 b = *(const float4*)&ks[h][tx * 4];
                acc[0][0] += a.x * b.x; acc[0][1] += a.x * b.y; acc[0][2] += a.x * b.z; acc[0][3] += a.x * b.w;
                acc[1][0] += a.y * b.x; acc[1][1] += a.y * b.y; acc[1][2] += a.y * b.z; acc[1][3] += a.y * b.w;
                acc[2][0] += a.z * b.x; acc[2][1] += a.z * b.y; acc[2][2] += a.z * b.z; acc[2][3] += a.z * b.w;
                acc[3][0] += a.w * b.x; acc[3][1] += a.w * b.y; acc[3][2] += a.w * b.z; acc[3][3] += a.w * b.w;
            }
        }

#pragma unroll
        for (int r = 0; r < 4; r++) {
#pragma unroll
            for (int j = 0; j < 4; j++) acc[r][j] *= 0.125f;
            float tm = fmaxf(fmaxf(acc[r][0], acc[r][1]), fmaxf(acc[r][2], acc[r][3]));
            float m2 = fmaxf(mv[r], tm);
            float s  = __expf(acc[r][0] - m2) + __expf(acc[r][1] - m2)
                     + __expf(acc[r][2] - m2) + __expf(acc[r][3] - m2);
            lv[r] = lv[r] * __expf(mv[r] - m2) + s;
            mv[r] = m2;
            float4 w;
            w.x = acc[r][0]; w.y = acc[r][1]; w.z = acc[r][2]; w.w = acc[r][3];
            *(float4*)&srow[(size_t)(m0 + ty * 4 + r) * P + n0 + tx * 4] = w;
        }
    }

    // reduce (max, sumexp) across the 64 threads (2 warps) owning each row group
    const int warp = tid >> 5;
#pragma unroll
    for (int off = 16; off > 0; off >>= 1) {
#pragma unroll
        for (int r = 0; r < 4; r++) {
            float mo = __shfl_xor_sync(0xffffffffu, mv[r], off);
            float lo = __shfl_xor_sync(0xffffffffu, lv[r], off);
            float M  = fmaxf(mv[r], mo);
            lv[r] = lv[r] * __expf(mv[r] - M) + lo * __expf(mo - M);
            mv[r] = M;
        }
    }
    if ((tid & 31) == 0) {
#pragma unroll
        for (int r = 0; r < 4; r++) { redm[warp][r] = mv[r]; redl[warp][r] = lv[r]; }
    }
    __syncthreads();
    if ((tid & 63) == 0) {
        const int w0 = ty * 2;
#pragma unroll
        for (int r = 0; r < 4; r++) {
            float ma = redm[w0][r], mb = redm[w0 + 1][r];
            float M  = fmaxf(ma, mb);
            float L  = redl[w0][r] * __expf(ma - M) + redl[w0 + 1][r] * __expf(mb - M);
            g_rowmax[(size_t)head * P + m0 + ty * 4 + r] = M;
            g_rowinv[(size_t)head * P + m0 + ty * 4 + r] = 1.0f / L;
        }
    }
}

// ============================================================
// K3: normalize probs in place + attn = probs @ V.
// Block = (head, 64 rows). K loop over 2048 in chunks of 32.
// ============================================================
__global__ void attn_kernel(float* __restrict__ probs)
{
    __shared__ __align__(16) float ps[32][68];   // [c][m]
    __shared__ __align__(16) float vs[32][68];   // [c][h]

    const int tid  = threadIdx.x;
    const int head = blockIdx.y;
    const int m0   = blockIdx.x * 64;
    const int ty   = tid >> 4;   // 0..15 -> rows ty*4..+3
    const int tx   = tid & 15;   // 0..15 -> h cols tx*4..+3

    const int lrow = tid >> 2;        // 0..63
    const int lc0  = (tid & 3) * 8;   // 0,8,16,24
    const float rmax = g_rowmax[(size_t)head * P + m0 + lrow];
    const float rinv = g_rowinv[(size_t)head * P + m0 + lrow];
    float* prow = probs + (size_t)head * P * P + (size_t)(m0 + lrow) * P;

    const int vc = tid >> 4;          // 0..15 -> rows vc, vc+16
    const int vh = (tid & 15) * 4;

    float acc[4][4];
#pragma unroll
    for (int i = 0; i < 4; i++)
#pragma unroll
        for (int j = 0; j < 4; j++) acc[i][j] = 0.0f;

    for (int k0 = 0; k0 < P; k0 += 32) {
        __syncthreads();
#pragma unroll
        for (int b = 0; b < 2; b++) {
            float4 s = *(const float4*)&prow[k0 + lc0 + b * 4];
            float4 p;
            p.x = __expf(s.x - rmax) * rinv;
            p.y = __expf(s.y - rmax) * rinv;
            p.z = __expf(s.z - rmax) * rinv;
            p.w = __expf(s.w - rmax) * rinv;
            *(float4*)&prow[k0 + lc0 + b * 4] = p;
            ps[lc0 + b * 4 + 0][lrow] = p.x; ps[lc0 + b * 4 + 1][lrow] = p.y;
            ps[lc0 + b * 4 + 2][lrow] = p.z; ps[lc0 + b * 4 + 3][lrow] = p.w;
        }
#pragma unroll
        for (int b = 0; b < 2; b++) {
            const int c = vc + b * 16;
            float4 vv = *(const float4*)&g_v[(size_t)(k0 + c) * H + vh];
            *(float4*)&vs[c][vh] = vv;
        }
        __syncthreads();
#pragma unroll
        for (int c = 0; c < 32; c++) {
            float4 a = *(const float4*)&ps[c][ty * 4];
            float4 b = *(const float4*)&vs[c][tx * 4];
            acc[0][0] += a.x * b.x; acc[0][1] += a.x * b.y; acc[0][2] += a.x * b.z; acc[0][3] += a.x * b.w;
            acc[1][0] += a.y * b.x; acc[1][1] += a.y * b.y; acc[1][2] += a.y * b.z; acc[1][3] += a.y * b.w;
            acc[2][0] += a.z * b.x; acc[2][1] += a.z * b.y; acc[2][2] += a.z * b.z; acc[2][3] += a.z * b.w;
            acc[3][0] += a.w * b.x; acc[3][1] += a.w * b.y; acc[3][2] += a.w * b.z; acc[3][3] += a.w * b.w;
        }
    }

#pragma unroll
    for (int i = 0; i < 4; i++) {
        float4 o;
        o.x = acc[i][0]; o.y = acc[i][1]; o.z = acc[i][2]; o.w = acc[i][3];
        *(float4*)&g_attn[((size_t)(m0 + ty * 4 + i) * NQ + head) * H + tx * 4] = o;
    }
}

// ============================================================
// K4: out = merged @ Wo^T + bo.   merged[p][q*64+h] = g_attn (contiguous).
// GEMM M=2048, N=64, K=768.  Tile 64x64, 256 thr, 4x4 micro.
// ============================================================
__global__ void out_kernel(const float* __restrict__ Wo,
                           const float* __restrict__ bo,
                           float* __restrict__ out)
{
    __shared__ __align__(16) float as_[32][68];  // [k][m]
    __shared__ __align__(16) float ws[32][68];   // [k][n]

    const int tid = threadIdx.x;
    const int m0  = blockIdx.x * 64;
    const int ty  = tid >> 4;
    const int tx  = tid & 15;

    const int lrow = tid >> 2;
    const int lc0  = (tid & 3) * 8;
    const int wn   = tid & 63;
    const int wk0  = (tid >> 6) * 8;

    float acc[4][4];
#pragma unroll
    for (int i = 0; i < 4; i++)
#pragma unroll
        for (int j = 0; j < 4; j++) acc[i][j] = 0.0f;

    for (int k0 = 0; k0 < NQ * H; k0 += 32) {
        __syncthreads();
#pragma unroll
        for (int b = 0; b < 2; b++) {
            float4 av = *(const float4*)&g_attn[(size_t)(m0 + lrow) * (NQ * H) + k0 + lc0 + b * 4];
            as_[lc0 + b * 4 + 0][lrow] = av.x; as_[lc0 + b * 4 + 1][lrow] = av.y;
            as_[lc0 + b * 4 + 2][lrow] = av.z; as_[lc0 + b * 4 + 3][lrow] = av.w;
        }
#pragma unroll
        for (int b = 0; b < 2; b++) {
            const int kq = wk0 + b * 4;
            float4 wv = *(const float4*)&Wo[(size_t)wn * (NQ * H) + k0 + kq];
            ws[kq + 0][wn] = wv.x; ws[kq + 1][wn] = wv.y;
            ws[kq + 2][wn] = wv.z; ws[kq + 3][wn] = wv.w;
        }
        __syncthreads();
#pragma unroll
        for (int k = 0; k < 32; k++) {
            float4 a = *(const float4*)&as_[k][ty * 4];
            float4 b = *(const float4*)&ws[k][tx * 4];
            acc[0][0] += a.x * b.x; acc[0][1] += a.x * b.y; acc[0][2] += a.x * b.z; acc[0][3] += a.x * b.w;
            acc[1][0] += a.y * b.x; acc[1][1] += a.y * b.y; acc[1][2] += a.y * b.z; acc[1][3] += a.y * b.w;
            acc[2][0] += a.z * b.x; acc[2][1] += a.z * b.y; acc[2][2] += a.z * b.z; acc[2][3] += a.z * b.w;
            acc[3][0] += a.w * b.x; acc[3][1] += a.w * b.y; acc[3][2] += a.w * b.z; acc[3][3] += a.w * b.w;
        }
    }

    const float4 bb = *(const float4*)&bo[tx * 4];
#pragma unroll
    for (int i = 0; i < 4; i++) {
        float4 o;
        o.x = acc[i][0] + bb.x; o.y = acc[i][1] + bb.y;
        o.z = acc[i][2] + bb.z; o.w = acc[i][3] + bb.w;
        *(float4*)&out[(size_t)(m0 + ty * 4 + i) * H + tx * 4] = o;
    }
}

// ============================================================
extern "C" void kernel_launch(void* const* d_in, const int* in_sizes, int n_in,
                              void* d_out, int out_size)
{
    const float* x  = (const float*)d_in[0];
    const float* Wq = (const float*)d_in[1];
    const float* bq = (const float*)d_in[2];
    const float* Wk = (const float*)d_in[3];
    const float* bk = (const float*)d_in[4];
    const float* Wv = (const float*)d_in[5];
    const float* bv = (const float*)d_in[6];
    const float* Wo = (const float*)d_in[7];
    const float* bo = (const float*)d_in[8];

    float* out   = (float*)d_out;          // [2048, 64]
    float* probs = out + (size_t)P * H;    // [12, 2048, 2048]

    qkv_kernel   <<<dim3(32, 14), 256>>>(x, Wq, bq, Wk, bk, Wv, bv);
    scores_kernel<<<dim3(128, 12), 256>>>(probs);
    attn_kernel  <<<dim3(32, 12), 256>>>(probs);
    out_kernel   <<<dim3(32, 1), 256>>>(Wo, bo, out);
}

// round 4
// speedup vs baseline: 1.7489x; 1.7489x over previous
#include <cuda_runtime.h>
#include <cuda_bf16.h>
#include <math.h>
#include <cstdint>

#define P  2048
#define E  768
#define H  64
#define NQ 12

// ---------------- scratch (static device globals) ----------------
__device__ __align__(16) float g_q[NQ * P * H];
__device__ __align__(16) float g_k[P * H];
__device__ __align__(16) float g_v[P * H];
__device__ __align__(16) float g_attn[P * NQ * H];
__device__ float g_rowmax[NQ * P];
__device__ float g_rowinv[NQ * P];
__device__ __align__(16) __nv_bfloat16 g_qhi[NQ * P * H];
__device__ __align__(16) __nv_bfloat16 g_qlo[NQ * P * H];
__device__ __align__(16) __nv_bfloat16 g_khi[P * H];
__device__ __align__(16) __nv_bfloat16 g_klo[P * H];
__device__ __align__(16) __nv_bfloat16 g_vthi[H * P];   // [h][p]
__device__ __align__(16) __nv_bfloat16 g_vtlo[H * P];

// mma.sync m16n8k16 row.col f32.bf16.bf16.f32
#define MMA16816(C, A0, A1, A2, A3, B0, B1) \
    asm volatile("mma.sync.aligned.m16n8k16.row.col.f32.bf16.bf16.f32 " \
        "{%0,%1,%2,%3}, {%4,%5,%6,%7}, {%8,%9}, {%0,%1,%2,%3};" \
        : "+f"((C)[0]), "+f"((C)[1]), "+f"((C)[2]), "+f"((C)[3]) \
        : "r"(A0), "r"(A1), "r"(A2), "r"(A3), "r"(B0), "r"(B1))

__device__ __forceinline__ uint32_t pk2(__nv_bfloat16 a, __nv_bfloat16 b) {
    __nv_bfloat162 t = __halves2bfloat162(a, b);
    return *reinterpret_cast<uint32_t*>(&t);
}

// ============================================================
// K1: fused QKV projection (scalar fp32, proven correct in R1)
// ============================================================
__global__ void qkv_kernel(const float* __restrict__ x,
                           const float* __restrict__ Wq, const float* __restrict__ bq,
                           const float* __restrict__ Wk, const float* __restrict__ bk,
                           const float* __restrict__ Wv, const float* __restrict__ bv)
{
    __shared__ __align__(16) float Xs[16][68];
    __shared__ __align__(16) float Ws[16][68];

    const int tid = threadIdx.x;
    const int m0  = blockIdx.x * 64;
    const int nt  = blockIdx.y;

    const float* W;
    const float* bias;
    if (nt < 12)      { W = Wq + (size_t)nt * 64 * E; bias = bq + nt * 64; }
    else if (nt == 12){ W = Wk; bias = bk; }
    else              { W = Wv; bias = bv; }

    const int ty = tid >> 4;
    const int tx = tid & 15;
    const int lr = tid & 63;
    const int lk = (tid >> 6) * 4;

    float acc[4][4];
#pragma unroll
    for (int i = 0; i < 4; i++)
#pragma unroll
        for (int j = 0; j < 4; j++) acc[i][j] = 0.0f;

    for (int kk = 0; kk < E; kk += 16) {
        __syncthreads();
        {
            float4 xv = *(const float4*)&x[(size_t)(m0 + lr) * E + kk + lk];
            Xs[lk + 0][lr] = xv.x; Xs[lk + 1][lr] = xv.y;
            Xs[lk + 2][lr] = xv.z; Xs[lk + 3][lr] = xv.w;
            float4 wv = *(const float4*)&W[(size_t)lr * E + kk + lk];
            Ws[lk + 0][lr] = wv.x; Ws[lk + 1][lr] = wv.y;
            Ws[lk + 2][lr] = wv.z; Ws[lk + 3][lr] = wv.w;
        }
        __syncthreads();
#pragma unroll
        for (int k = 0; k < 16; k++) {
            float4 a = *(const float4*)&Xs[k][ty * 4];
            float4 b = *(const float4*)&Ws[k][tx * 4];
            acc[0][0] += a.x * b.x; acc[0][1] += a.x * b.y; acc[0][2] += a.x * b.z; acc[0][3] += a.x * b.w;
            acc[1][0] += a.y * b.x; acc[1][1] += a.y * b.y; acc[1][2] += a.y * b.z; acc[1][3] += a.y * b.w;
            acc[2][0] += a.z * b.x; acc[2][1] += a.z * b.y; acc[2][2] += a.z * b.z; acc[2][3] += a.z * b.w;
            acc[3][0] += a.w * b.x; acc[3][1] += a.w * b.y; acc[3][2] += a.w * b.z; acc[3][3] += a.w * b.w;
        }
    }

    const float4 bb = *(const float4*)&bias[tx * 4];
#pragma unroll
    for (int i = 0; i < 4; i++) {
        float4 o;
        o.x = acc[i][0] + bb.x; o.y = acc[i][1] + bb.y;
        o.z = acc[i][2] + bb.z; o.w = acc[i][3] + bb.w;
        const int m = m0 + ty * 4 + i;
        if (nt < 12)      *(float4*)&g_q[((size_t)nt * P + m) * H + tx * 4] = o;
        else if (nt == 12)*(float4*)&g_k[(size_t)m * H + tx * 4] = o;
        else              *(float4*)&g_v[(size_t)m * H + tx * 4] = o;
    }
}

// ============================================================
// K2: prep — bf16 hi/lo splits (q pre-scaled by exact 0.125, v transposed)
// ============================================================
__global__ void prep_kernel()
{
    const int NQE = NQ * P * H;
    int i = blockIdx.x * 256 + threadIdx.x;
    if (i < NQE) {
        float v = g_q[i] * 0.125f;
        __nv_bfloat16 hi = __float2bfloat16(v);
        g_qhi[i] = hi;
        g_qlo[i] = __float2bfloat16(v - __bfloat162float(hi));
    } else if (i < NQE + P * H) {
        int j = i - NQE;
        float v = g_k[j];
        __nv_bfloat16 hi = __float2bfloat16(v);
        g_khi[j] = hi;
        g_klo[j] = __float2bfloat16(v - __bfloat162float(hi));
    } else if (i < NQE + 2 * P * H) {
        int j = i - NQE - P * H;
        int p = j >> 6, h = j & 63;
        float v = g_v[j];
        __nv_bfloat16 hi = __float2bfloat16(v);
        g_vthi[h * P + p] = hi;
        g_vtlo[h * P + p] = __float2bfloat16(v - __bfloat162float(hi));
    }
}

// ============================================================
// K3: scores via mma.sync bf16x3.
// grid (32, 12). Block = 64 q rows × 2048 k cols (32 chunks of 64).
// Writes raw scaled scores to probs region; online (max, sumexp) -> stats.
// 8 warps: wm = wid&3 (m16 group), wn = wid>>2 (32-col half).
// ============================================================
__global__ void __launch_bounds__(256) scores2_kernel(float* __restrict__ probs)
{
    __shared__ __nv_bfloat16 Qh[64][72], Ql[64][72];
    __shared__ __nv_bfloat16 Kh[64][72], Kl[64][72];
    __shared__ float sm_m[8][16], sm_l[8][16];

    const int tid  = threadIdx.x;
    const int wid  = tid >> 5;
    const int lane = tid & 31;
    const int g    = lane >> 2;
    const int tig  = lane & 3;
    const int head = blockIdx.y;
    const int m0   = blockIdx.x * 64;
    const int wm   = wid & 3;
    const int wn   = wid >> 2;

    // stage Q hi/lo (64 rows x 64 bf16)
    {
        const __nv_bfloat16* qh = g_qhi + ((size_t)head * P + m0) * H;
        const __nv_bfloat16* ql = g_qlo + ((size_t)head * P + m0) * H;
#pragma unroll
        for (int i = 0; i < 4; i++) {
            int ch = tid + i * 256;          // 0..1023 (64 rows x 16 uint2)
            int r = ch >> 4, c = (ch & 15) * 4;
            *(uint2*)&Qh[r][c] = *(const uint2*)(qh + r * H + c);
            *(uint2*)&Ql[r][c] = *(const uint2*)(ql + r * H + c);
        }
    }

    float m1 = -3e38f, l1 = 0.0f, m2 = -3e38f, l2 = 0.0f;
    float* ob = probs + (size_t)head * P * P;

    for (int it = 0; it < 32; it++) {
        const int n0 = it * 64;
        __syncthreads();   // previous iter's frag reads done before restage
        {
            const __nv_bfloat16* kh = g_khi + (size_t)n0 * H;
            const __nv_bfloat16* kl = g_klo + (size_t)n0 * H;
#pragma unroll
            for (int i = 0; i < 4; i++) {
                int ch = tid + i * 256;
                int r = ch >> 4, c = (ch & 15) * 4;
                *(uint2*)&Kh[r][c] = *(const uint2*)(kh + r * H + c);
                *(uint2*)&Kl[r][c] = *(const uint2*)(kl + r * H + c);
            }
        }
        __syncthreads();

        float acc[4][4];
#pragma unroll
        for (int tn = 0; tn < 4; tn++)
#pragma unroll
            for (int j = 0; j < 4; j++) acc[tn][j] = 0.0f;

#pragma unroll
        for (int ks = 0; ks < 4; ks++) {
            const int kc = ks * 16 + 2 * tig;
            const int ra = wm * 16 + g;
            uint32_t ah0 = *(const uint32_t*)&Qh[ra][kc];
            uint32_t ah1 = *(const uint32_t*)&Qh[ra + 8][kc];
            uint32_t ah2 = *(const uint32_t*)&Qh[ra][kc + 8];
            uint32_t ah3 = *(const uint32_t*)&Qh[ra + 8][kc + 8];
            uint32_t al0 = *(const uint32_t*)&Ql[ra][kc];
            uint32_t al1 = *(const uint32_t*)&Ql[ra + 8][kc];
            uint32_t al2 = *(const uint32_t*)&Ql[ra][kc + 8];
            uint32_t al3 = *(const uint32_t*)&Ql[ra + 8][kc + 8];
#pragma unroll
            for (int tn = 0; tn < 4; tn++) {
                const int nb = wn * 32 + tn * 8 + g;
                uint32_t bh0 = *(const uint32_t*)&Kh[nb][kc];
                uint32_t bh1 = *(const uint32_t*)&Kh[nb][kc + 8];
                uint32_t bl0 = *(const uint32_t*)&Kl[nb][kc];
                uint32_t bl1 = *(const uint32_t*)&Kl[nb][kc + 8];
                MMA16816(acc[tn], ah0, ah1, ah2, ah3, bh0, bh1);
                MMA16816(acc[tn], ah0, ah1, ah2, ah3, bl0, bl1);
                MMA16816(acc[tn], al0, al1, al2, al3, bh0, bh1);
            }
        }

        // online stats (thread owns rows r1=wm*16+g, r2=r1+8 over its 8 cols)
        {
            float a1 = fmaxf(acc[0][0], acc[0][1]);
            float a2 = fmaxf(acc[0][2], acc[0][3]);
#pragma unroll
            for (int tn = 1; tn < 4; tn++) {
                a1 = fmaxf(a1, fmaxf(acc[tn][0], acc[tn][1]));
                a2 = fmaxf(a2, fmaxf(acc[tn][2], acc[tn][3]));
            }
            if (a1 > m1) { l1 *= __expf(m1 - a1); m1 = a1; }
            if (a2 > m2) { l2 *= __expf(m2 - a2); m2 = a2; }
#pragma unroll
            for (int tn = 0; tn < 4; tn++) {
                l1 += __expf(acc[tn][0] - m1) + __expf(acc[tn][1] - m1);
                l2 += __expf(acc[tn][2] - m2) + __expf(acc[tn][3] - m2);
            }
        }
        // raw score writes
        {
            const int r1 = m0 + wm * 16 + g;
            const int r2 = r1 + 8;
#pragma unroll
            for (int tn = 0; tn < 4; tn++) {
                const int col = n0 + wn * 32 + tn * 8 + 2 * tig;
                *(float2*)&ob[(size_t)r1 * P + col] = make_float2(acc[tn][0], acc[tn][1]);
                *(float2*)&ob[(size_t)r2 * P + col] = make_float2(acc[tn][2], acc[tn][3]);
            }
        }
    }

    // reduce (m,l) across the 4 tig lanes (same rows)
#pragma unroll
    for (int off = 1; off <= 2; off <<= 1) {
        float mo = __shfl_xor_sync(0xffffffffu, m1, off);
        float lo = __shfl_xor_sync(0xffffffffu, l1, off);
        float M  = fmaxf(m1, mo);
        l1 = l1 * __expf(m1 - M) + lo * __expf(mo - M);
        m1 = M;
        mo = __shfl_xor_sync(0xffffffffu, m2, off);
        lo = __shfl_xor_sync(0xffffffffu, l2, off);
        M  = fmaxf(m2, mo);
        l2 = l2 * __expf(m2 - M) + lo * __expf(mo - M);
        m2 = M;
    }
    if (tig == 0) {
        sm_m[wid][g] = m1;     sm_l[wid][g] = l1;
        sm_m[wid][8 + g] = m2; sm_l[wid][8 + g] = l2;
    }
    __syncthreads();
    if (tid < 64) {
        int wmv = tid >> 4, ri = tid & 15;
        float ma = sm_m[wmv][ri],     la = sm_l[wmv][ri];
        float mb = sm_m[wmv + 4][ri], lb = sm_l[wmv + 4][ri];
        float M = fmaxf(ma, mb);
        float L = la * __expf(ma - M) + lb * __expf(mb - M);
        g_rowmax[(size_t)head * P + m0 + tid] = M;
        g_rowinv[(size_t)head * P + m0 + tid] = 1.0f / L;
    }
}

// ============================================================
// K4: attn via mma.sync bf16x3. Normalizes probs in place + attn = probs @ V.
// grid (32, 12). Block = 64 rows × K loop of 32 chunks of 64 tokens.
// ============================================================
__global__ void __launch_bounds__(256) attn2_kernel(float* __restrict__ probs)
{
    __shared__ __nv_bfloat16 Ph[64][72], Pl[64][72];
    __shared__ __nv_bfloat16 Vh[64][72], Vl[64][72];
    __shared__ float srm[64], sri[64];

    const int tid  = threadIdx.x;
    const int wid  = tid >> 5;
    const int lane = tid & 31;
    const int g    = lane >> 2;
    const int tig  = lane & 3;
    const int head = blockIdx.y;
    const int m0   = blockIdx.x * 64;
    const int wm   = wid & 3;
    const int wn   = wid >> 2;

    if (tid < 64) {
        srm[tid] = g_rowmax[(size_t)head * P + m0 + tid];
        sri[tid] = g_rowinv[(size_t)head * P + m0 + tid];
    }

    float acc[4][4];
#pragma unroll
    for (int tn = 0; tn < 4; tn++)
#pragma unroll
        for (int j = 0; j < 4; j++) acc[tn][j] = 0.0f;

    float* prow0 = probs + (size_t)head * P * P + (size_t)m0 * P;

    for (int it = 0; it < 32; it++) {
        const int k0 = it * 64;
        __syncthreads();   // prev frag reads done (and srm visible on first iter)

        // stage P: read raw, normalize, write back, split hi/lo
#pragma unroll
        for (int i = 0; i < 4; i++) {
            int ch = tid + i * 256;          // 0..1023 (64 rows x 16 float4)
            int r = ch >> 4, c = (ch & 15) * 4;
            float* gp = prow0 + (size_t)r * P + k0 + c;
            float4 s = *(const float4*)gp;
            float rm = srm[r], ri = sri[r];
            float4 p;
            p.x = __expf(s.x - rm) * ri;
            p.y = __expf(s.y - rm) * ri;
            p.z = __expf(s.z - rm) * ri;
            p.w = __expf(s.w - rm) * ri;
            *(float4*)gp = p;
            __nv_bfloat16 h0 = __float2bfloat16(p.x), h1 = __float2bfloat16(p.y);
            __nv_bfloat16 h2 = __float2bfloat16(p.z), h3 = __float2bfloat16(p.w);
            __nv_bfloat16 q0 = __float2bfloat16(p.x - __bfloat162float(h0));
            __nv_bfloat16 q1 = __float2bfloat16(p.y - __bfloat162float(h1));
            __nv_bfloat16 q2 = __float2bfloat16(p.z - __bfloat162float(h2));
            __nv_bfloat16 q3 = __float2bfloat16(p.w - __bfloat162float(h3));
            *(uint2*)&Ph[r][c] = make_uint2(pk2(h0, h1), pk2(h2, h3));
            *(uint2*)&Pl[r][c] = make_uint2(pk2(q0, q1), pk2(q2, q3));
        }
        // stage V: [h=64 rows][64 tokens] from transposed layout
#pragma unroll
        for (int i = 0; i < 4; i++) {
            int ch = tid + i * 256;
            int r = ch >> 4, c = (ch & 15) * 4;
            *(uint2*)&Vh[r][c] = *(const uint2*)(g_vthi + (size_t)r * P + k0 + c);
            *(uint2*)&Vl[r][c] = *(const uint2*)(g_vtlo + (size_t)r * P + k0 + c);
        }
        __syncthreads();

#pragma unroll
        for (int ks = 0; ks < 4; ks++) {
            const int kc = ks * 16 + 2 * tig;
            const int ra = wm * 16 + g;
            uint32_t ah0 = *(const uint32_t*)&Ph[ra][kc];
            uint32_t ah1 = *(const uint32_t*)&Ph[ra + 8][kc];
            uint32_t ah2 = *(const uint32_t*)&Ph[ra][kc + 8];
            uint32_t ah3 = *(const uint32_t*)&Ph[ra + 8][kc + 8];
            uint32_t al0 = *(const uint32_t*)&Pl[ra][kc];
            uint32_t al1 = *(const uint32_t*)&Pl[ra + 8][kc];
            uint32_t al2 = *(const uint32_t*)&Pl[ra][kc + 8];
            uint32_t al3 = *(const uint32_t*)&Pl[ra + 8][kc + 8];
#pragma unroll
            for (int tn = 0; tn < 4; tn++) {
                const int nb = wn * 32 + tn * 8 + g;
                uint32_t bh0 = *(const uint32_t*)&Vh[nb][kc];
                uint32_t bh1 = *(const uint32_t*)&Vh[nb][kc + 8];
                uint32_t bl0 = *(const uint32_t*)&Vl[nb][kc];
                uint32_t bl1 = *(const uint32_t*)&Vl[nb][kc + 8];
                MMA16816(acc[tn], ah0, ah1, ah2, ah3, bh0, bh1);
                MMA16816(acc[tn], ah0, ah1, ah2, ah3, bl0, bl1);
                MMA16816(acc[tn], al0, al1, al2, al3, bh0, bh1);
            }
        }
    }

    // epilogue: write attn to merged layout [p][head][h]
    {
        const int r1 = m0 + wm * 16 + g;
        const int r2 = r1 + 8;
#pragma unroll
        for (int tn = 0; tn < 4; tn++) {
            const int col = wn * 32 + tn * 8 + 2 * tig;
            *(float2*)&g_attn[((size_t)r1 * NQ + head) * H + col] = make_float2(acc[tn][0], acc[tn][1]);
            *(float2*)&g_attn[((size_t)r2 * NQ + head) * H + col] = make_float2(acc[tn][2], acc[tn][3]);
        }
    }
}

// ============================================================
// K5: out = merged @ Wo^T + bo (scalar fp32, proven correct in R1)
// ============================================================
__global__ void out_kernel(const float* __restrict__ Wo,
                           const float* __restrict__ bo,
                           float* __restrict__ out)
{
    __shared__ __align__(16) float as_[32][68];
    __shared__ __align__(16) float ws[32][68];

    const int tid = threadIdx.x;
    const int m0  = blockIdx.x * 64;
    const int ty  = tid >> 4;
    const int tx  = tid & 15;

    const int lrow = tid >> 2;
    const int lc0  = (tid & 3) * 8;
    const int wn   = tid & 63;
    const int wk0  = (tid >> 6) * 8;

    float acc[4][4];
#pragma unroll
    for (int i = 0; i < 4; i++)
#pragma unroll
        for (int j = 0; j < 4; j++) acc[i][j] = 0.0f;

    for (int k0 = 0; k0 < NQ * H; k0 += 32) {
        __syncthreads();
#pragma unroll
        for (int b = 0; b < 2; b++) {
            float4 av = *(const float4*)&g_attn[(size_t)(m0 + lrow) * (NQ * H) + k0 + lc0 + b * 4];
            as_[lc0 + b * 4 + 0][lrow] = av.x; as_[lc0 + b * 4 + 1][lrow] = av.y;
            as_[lc0 + b * 4 + 2][lrow] = av.z; as_[lc0 + b * 4 + 3][lrow] = av.w;
        }
#pragma unroll
        for (int b = 0; b < 2; b++) {
            const int kq = wk0 + b * 4;
            float4 wv = *(const float4*)&Wo[(size_t)wn * (NQ * H) + k0 + kq];
            ws[kq + 0][wn] = wv.x; ws[kq + 1][wn] = wv.y;
            ws[kq + 2][wn] = wv.z; ws[kq + 3][wn] = wv.w;
        }
        __syncthreads();
#pragma unroll
        for (int k = 0; k < 32; k++) {
            float4 a = *(const float4*)&as_[k][ty * 4];
            float4 b = *(const float4*)&ws[k][tx * 4];
            acc[0][0] += a.x * b.x; acc[0][1] += a.x * b.y; acc[0][2] += a.x * b.z; acc[0][3] += a.x * b.w;
            acc[1][0] += a.y * b.x; acc[1][1] += a.y * b.y; acc[1][2] += a.y * b.z; acc[1][3] += a.y * b.w;
            acc[2][0] += a.z * b.x; acc[2][1] += a.z * b.y; acc[2][2] += a.z * b.z; acc[2][3] += a.z * b.w;
            acc[3][0] += a.w * b.x; acc[3][1] += a.w * b.y; acc[3][2] += a.w * b.z; acc[3][3] += a.w * b.w;
        }
    }

    const float4 bb = *(const float4*)&bo[tx * 4];
#pragma unroll
    for (int i = 0; i < 4; i++) {
        float4 o;
        o.x = acc[i][0] + bb.x; o.y = acc[i][1] + bb.y;
        o.z = acc[i][2] + bb.z; o.w = acc[i][3] + bb.w;
        *(float4*)&out[(size_t)(m0 + ty * 4 + i) * H + tx * 4] = o;
    }
}

// ============================================================
extern "C" void kernel_launch(void* const* d_in, const int* in_sizes, int n_in,
                              void* d_out, int out_size)
{
    const float* x  = (const float*)d_in[0];
    const float* Wq = (const float*)d_in[1];
    const float* bq = (const float*)d_in[2];
    const float* Wk = (const float*)d_in[3];
    const float* bk = (const float*)d_in[4];
    const float* Wv = (const float*)d_in[5];
    const float* bv = (const float*)d_in[6];
    const float* Wo = (const float*)d_in[7];
    const float* bo = (const float*)d_in[8];

    float* out   = (float*)d_out;          // [2048, 64]
    float* probs = out + (size_t)P * H;    // [12, 2048, 2048]

    qkv_kernel    <<<dim3(32, 14), 256>>>(x, Wq, bq, Wk, bk, Wv, bv);
    prep_kernel   <<<7168, 256>>>();
    scores2_kernel<<<dim3(32, 12), 256>>>(probs);
    attn2_kernel  <<<dim3(32, 12), 256>>>(probs);
    out_kernel    <<<dim3(32, 1), 256>>>(Wo, bo, out);
}